// round 1
// baseline (speedup 1.0000x reference)
#include <cuda_runtime.h>
#include <cstring>

#define S_LEN 512
#define BATCH 64
#define IDIM  256
#define HID   512
#define GH    1536   // 3*HID
#define ODIM  512    // 2*O

// ---------------- scratch (static device globals; no allocation) -------------
__device__ float    g_gi[(size_t)BATCH * S_LEN * GH];   // [B*S][3H]  (row = b*512+s)
__device__ float    g_hs[(size_t)S_LEN * BATCH * HID];  // [S][B][H]  (row = s*64+b)
__device__ unsigned g_bar[4 * S_LEN];                   // per-group per-step arrival counters

// ---------------- packed f32x2 FMA (full-rate fp32 on sm_100a) ---------------
__device__ __forceinline__ float2 ffma2(float2 a, float2 b, float2 c) {
#if defined(__CUDA_ARCH__) && (__CUDA_ARCH__ >= 1000)
    unsigned long long au, bu, cu, du;
    memcpy(&au, &a, 8); memcpy(&bu, &b, 8); memcpy(&cu, &c, 8);
    asm("fma.rn.f32x2 %0, %1, %2, %3;" : "=l"(du) : "l"(au), "l"(bu), "l"(cu));
    float2 d; memcpy(&d, &du, 8);
    return d;
#else
    return make_float2(fmaf(a.x, b.x, c.x), fmaf(a.y, b.y, c.y));
#endif
}

// =============================================================================
// Tiled GEMM: C[M][N] = A[M][K] * B[N][K]^T + bias[N]
// 128x128 CTA tile, BLK_K=16, 256 threads, 8x8 per-thread tile, f32x2 FMAs.
// MODE 0: C row-major with stride GH  (gi output)
// MODE 1: C row r=(s*64+b) remapped to out[(b*512+s)*512 + n] (final output)
// =============================================================================
template<int KDIM, int MODE>
__global__ __launch_bounds__(256)
void gemm_tn(const float* __restrict__ A, const float* __restrict__ B,
             const float* __restrict__ bias, float* __restrict__ C)
{
    __shared__ float As[16 * 132];
    __shared__ float Bs[16 * 132];

    const int tid = threadIdx.x;
    const int m0 = blockIdx.y * 128;
    const int n0 = blockIdx.x * 128;
    const int lr = tid >> 2;      // 0..63
    const int lc = tid & 3;       // float4 column in k
    const int tx = tid & 15;
    const int ty = tid >> 4;

    const float* Ap = A + (size_t)(m0 + lr) * KDIM + lc * 4;
    const float* Bp = B + (size_t)(n0 + lr) * KDIM + lc * 4;

    float2 c2[8][4];
#pragma unroll
    for (int i = 0; i < 8; i++)
#pragma unroll
        for (int j = 0; j < 4; j++) c2[i][j] = make_float2(0.f, 0.f);

    float4 pa0 = *(const float4*)(Ap);
    float4 pa1 = *(const float4*)(Ap + (size_t)64 * KDIM);
    float4 pb0 = *(const float4*)(Bp);
    float4 pb1 = *(const float4*)(Bp + (size_t)64 * KDIM);

    const int KT = KDIM / 16;
    for (int kt = 0; kt < KT; kt++) {
        // stage current tile (transpose into [k][m]/[k][n])
        {
            const float* a0 = (const float*)&pa0;
            const float* a1 = (const float*)&pa1;
            const float* b0 = (const float*)&pb0;
            const float* b1 = (const float*)&pb1;
#pragma unroll
            for (int j = 0; j < 4; j++) {
                As[(lc * 4 + j) * 132 + lr]      = a0[j];
                As[(lc * 4 + j) * 132 + lr + 64] = a1[j];
                Bs[(lc * 4 + j) * 132 + lr]      = b0[j];
                Bs[(lc * 4 + j) * 132 + lr + 64] = b1[j];
            }
        }
        __syncthreads();
        if (kt + 1 < KT) {          // prefetch next tile into registers
            Ap += 16; Bp += 16;
            pa0 = *(const float4*)(Ap);
            pa1 = *(const float4*)(Ap + (size_t)64 * KDIM);
            pb0 = *(const float4*)(Bp);
            pb1 = *(const float4*)(Bp + (size_t)64 * KDIM);
        }
#pragma unroll
        for (int k = 0; k < 16; k++) {
            float4 a0 = *(const float4*)&As[k * 132 + ty * 8];
            float4 a1 = *(const float4*)&As[k * 132 + ty * 8 + 4];
            float4 b0 = *(const float4*)&Bs[k * 132 + tx * 8];
            float4 b1 = *(const float4*)&Bs[k * 132 + tx * 8 + 4];
            float av[8] = {a0.x, a0.y, a0.z, a0.w, a1.x, a1.y, a1.z, a1.w};
            float2 bv[4] = {{b0.x, b0.y}, {b0.z, b0.w}, {b1.x, b1.y}, {b1.z, b1.w}};
#pragma unroll
            for (int i = 0; i < 8; i++) {
                float2 ad = make_float2(av[i], av[i]);
#pragma unroll
                for (int j = 0; j < 4; j++) c2[i][j] = ffma2(ad, bv[j], c2[i][j]);
            }
        }
        __syncthreads();
    }

    // epilogue: + bias, store
    const int nb = n0 + tx * 8;
    float2 bb[4];
#pragma unroll
    for (int j = 0; j < 4; j++) bb[j] = make_float2(bias[nb + 2 * j], bias[nb + 2 * j + 1]);

#pragma unroll
    for (int i = 0; i < 8; i++) {
        int r = m0 + ty * 8 + i;
        size_t base;
        if (MODE == 0) {
            base = (size_t)r * GH + nb;
        } else {
            int s = r >> 6, b = r & 63;                 // r = s*64+b
            base = ((size_t)(b * S_LEN + s)) * ODIM + nb;
        }
#pragma unroll
        for (int j = 0; j < 4; j++) {
            float2 v = make_float2(c2[i][j].x + bb[j].x, c2[i][j].y + bb[j].y);
            *(float2*)&C[base + 2 * j] = v;
        }
    }
}

// =============================================================================
// GRU scan: 4 groups x 32 CTAs. Group g owns batches [16g,16g+16); CTA slice
// owns 16 hidden units (rows j, 512+j, 1024+j of w_hh), weights REGISTER-
// resident for the whole scan. 256 threads = 16 j x 16 K-chunks (Kc=32).
// Per step: h (SMEM, [k][b] transposed) -> f32x2 partial dots -> SMEM K-reduce
// -> gates -> h_new to g_hs -> group barrier via L2 atomic counter.
// =============================================================================
__global__ __launch_bounds__(256, 1)
void gru_scan(const float* __restrict__ w_hh, const float* __restrict__ b_hh)
{
    extern __shared__ float sm[];
    float* sh_h = sm;                       // 512*18 floats (h transposed, padded)
    float* sred = sm + 512 * 18;            // 256*49 floats (partials)
    float* sg   = sred + 256 * 49;          // 768 floats (reduced gh)

    const int tid   = threadIdx.x;
    const int grp   = blockIdx.x >> 5;
    const int slice = blockIdx.x & 31;
    const int j0    = slice * 16;
    const int b0    = grp * 16;
    const int j_idx = tid & 15;             // hidden unit within slice
    const int k_idx = tid >> 4;             // K-chunk (32 k each)
    const int kb    = k_idx * 32;

    // ---- register-resident weight slice: 3 gates x 32 k --------------------
    float w[3][32];
#pragma unroll
    for (int g = 0; g < 3; g++) {
        const float* p = w_hh + (size_t)(g * HID + j0 + j_idx) * HID + kb;
#pragma unroll
        for (int q = 0; q < 8; q++) {
            float4 v = *(const float4*)(p + 4 * q);
            w[g][4 * q + 0] = v.x; w[g][4 * q + 1] = v.y;
            w[g][4 * q + 2] = v.z; w[g][4 * q + 3] = v.w;
        }
    }

    // gate-stage identity: thread -> (batch gbb, hidden gjj)
    const int gjj = tid >> 4;
    const int gbb = tid & 15;
    const float bh_r = b_hh[j0 + gjj];
    const float bh_z = b_hh[HID + j0 + gjj];
    const float bh_n = b_hh[2 * HID + j0 + gjj];

    // h0 = 0
    for (int i = tid; i < 512 * 18; i += 256) sh_h[i] = 0.f;
    __syncthreads();

    for (int s = 0; s < S_LEN; s++) {
        // prefetch gi for the gate stage (independent of this step's compute)
        const float* gip = g_gi + ((size_t)((b0 + gbb) * S_LEN + s)) * GH + j0 + gjj;
        float gir = gip[0], giz = gip[HID], gin = gip[2 * HID];

        // ---- partial dot products over this thread's K-chunk ---------------
        float2 acc[8][3];
#pragma unroll
        for (int bp = 0; bp < 8; bp++)
#pragma unroll
            for (int g = 0; g < 3; g++) acc[bp][g] = make_float2(0.f, 0.f);

#pragma unroll
        for (int kk = 0; kk < 32; kk++) {
            const float* hr = sh_h + (kb + kk) * 18;
            float2 wr = make_float2(w[0][kk], w[0][kk]);
            float2 wz = make_float2(w[1][kk], w[1][kk]);
            float2 wn = make_float2(w[2][kk], w[2][kk]);
#pragma unroll
            for (int bp = 0; bp < 8; bp++) {
                float2 h2 = *(const float2*)(hr + 2 * bp);
                acc[bp][0] = ffma2(h2, wr, acc[bp][0]);
                acc[bp][1] = ffma2(h2, wz, acc[bp][1]);
                acc[bp][2] = ffma2(h2, wn, acc[bp][2]);
            }
        }

        // ---- dump partials: red[tid*49 + o], o = b*3+gate (conflict-free) --
        {
            float* rp = sred + tid * 49;
#pragma unroll
            for (int bp = 0; bp < 8; bp++)
#pragma unroll
                for (int g = 0; g < 3; g++) {
                    rp[6 * bp + g]     = acc[bp][g].x;
                    rp[6 * bp + 3 + g] = acc[bp][g].y;
                }
        }
        __syncthreads();

        // ---- reduce across 16 K-chunks: 768 outputs, 3 per thread ----------
#pragma unroll
        for (int q = 0; q < 3; q++) {
            int oid = q * 256 + tid;
            int jj = oid / 48, o = oid % 48;
            float ssum = 0.f;
#pragma unroll
            for (int kk = 0; kk < 16; kk++) ssum += sred[(kk * 16 + jj) * 49 + o];
            sg[jj * 48 + o] = ssum;
        }
        __syncthreads();

        // ---- gates + state update ------------------------------------------
        {
            float ghr = sg[gjj * 48 + 3 * gbb + 0] + bh_r;
            float ghz = sg[gjj * 48 + 3 * gbb + 1] + bh_z;
            float ghn = sg[gjj * 48 + 3 * gbb + 2] + bh_n;
            float r = 1.f / (1.f + __expf(-(gir + ghr)));
            float z = 1.f / (1.f + __expf(-(giz + ghz)));
            float n = tanhf(gin + r * ghn);
            float hp = sh_h[(j0 + gjj) * 18 + gbb];
            float hn = (1.f - z) * n + z * hp;
            g_hs[((size_t)s * BATCH + b0 + gbb) * HID + j0 + gjj] = hn;
        }
        __threadfence();
        __syncthreads();

        // ---- group barrier (32 CTAs, per-step counter, memset-reset) -------
        {
            unsigned* ctr = &g_bar[grp * S_LEN + s];
            if (tid == 0) {
                atomicAdd(ctr, 1u);
                while (*(volatile unsigned*)ctr < 32u) { __nanosleep(32); }
            }
            __syncthreads();
        }

        // ---- reload full h for next step (transposed into SMEM) ------------
        if (s + 1 < S_LEN) {
            const float* hsrc = g_hs + (size_t)s * BATCH * HID + (size_t)b0 * HID;
            for (int i = tid; i < 16 * HID; i += 256) {
                int b = i >> 9, k = i & 511;
                sh_h[k * 18 + b] = hsrc[(size_t)b * HID + k];
            }
            __syncthreads();
        }
    }
}

// =============================================================================
extern "C" void kernel_launch(void* const* d_in, const int* in_sizes, int n_in,
                              void* d_out, int out_size)
{
    (void)in_sizes; (void)n_in; (void)out_size;
    const float* x     = (const float*)d_in[0];   // [64,512,256]
    const float* w_ih  = (const float*)d_in[1];   // [1536,256]
    const float* w_hh  = (const float*)d_in[2];   // [1536,512]
    const float* b_ih  = (const float*)d_in[3];   // [1536]
    const float* b_hh  = (const float*)d_in[4];   // [1536]
    const float* w_out = (const float*)d_in[5];   // [512,512]
    const float* b_out = (const float*)d_in[6];   // [512]
    float* out = (float*)d_out;                   // [64,512,256,2]

    void *p_gi = nullptr, *p_hs = nullptr, *p_bar = nullptr;
    cudaGetSymbolAddress(&p_gi, g_gi);
    cudaGetSymbolAddress(&p_hs, g_hs);
    cudaGetSymbolAddress(&p_bar, g_bar);

    // reset barrier counters (captured into the graph, runs every replay)
    cudaMemsetAsync(p_bar, 0, sizeof(unsigned) * 4 * S_LEN);

    cudaFuncSetAttribute(gru_scan, cudaFuncAttributeMaxDynamicSharedMemorySize, 90112);

    // Phase 1: gi = x @ w_ih^T + b_ih   (M=32768, N=1536, K=256)
    gemm_tn<IDIM, 0><<<dim3(GH / 128, (BATCH * S_LEN) / 128), 256>>>(
        x, w_ih, b_ih, (float*)p_gi);

    // Phase 2: 512-step GRU scan (persistent, 128 CTAs, group barriers)
    gru_scan<<<128, 256, 90112>>>(w_hh, b_hh);

    // Phase 3: out = hs @ w_out^T + b_out   (M=32768, N=512, K=512)
    gemm_tn<HID, 1><<<dim3(ODIM / 128, (BATCH * S_LEN) / 128), 256>>>(
        (const float*)p_hs, w_out, b_out, out);
}

// round 2
// speedup vs baseline: 1.2821x; 1.2821x over previous
#include <cuda_runtime.h>
#include <cstring>

#define S_LEN 512
#define BATCH 64
#define IDIM  256
#define HID   512
#define GH    1536   // 3*HID
#define ODIM  512    // 2*O

// ---------------- scratch (static device globals; no allocation) -------------
__device__ float    g_gi[(size_t)BATCH * S_LEN * GH];    // [B*S][3H]  (row = b*512+s)
__device__ float    g_hs[(size_t)S_LEN * BATCH * HID];   // [S][B][H]  (row = s*64+b) -> GEMM2
__device__ float    g_hsT[(size_t)S_LEN * 4 * HID * 16]; // [S][grp][k][b16] -> scan exchange
__device__ unsigned g_bar[4 * S_LEN];                    // per-group per-step arrival counters

// ---------------- packed f32x2 FMA (full-rate fp32 on sm_100a) ---------------
__device__ __forceinline__ float2 ffma2(float2 a, float2 b, float2 c) {
#if defined(__CUDA_ARCH__) && (__CUDA_ARCH__ >= 1000)
    unsigned long long au, bu, cu, du;
    memcpy(&au, &a, 8); memcpy(&bu, &b, 8); memcpy(&cu, &c, 8);
    asm("fma.rn.f32x2 %0, %1, %2, %3;" : "=l"(du) : "l"(au), "l"(bu), "l"(cu));
    float2 d; memcpy(&d, &du, 8);
    return d;
#else
    return make_float2(fmaf(a.x, b.x, c.x), fmaf(a.y, b.y, c.y));
#endif
}

// =============================================================================
// Tiled GEMM: C[M][N] = A[M][K] * B[N][K]^T + bias[N]
// 128x128 CTA tile, BLK_K=16, 256 threads, 8x8 per-thread tile (4+4 split to
// kill smem bank conflicts), f32x2 FMAs.
// MODE 0: C row-major with stride GH  (gi output)
// MODE 1: C row r=(s*64+b) remapped to out[(b*512+s)*512 + n] (final output)
// =============================================================================
template<int KDIM, int MODE>
__global__ __launch_bounds__(256)
void gemm_tn(const float* __restrict__ A, const float* __restrict__ B,
             const float* __restrict__ bias, float* __restrict__ C)
{
    __shared__ float As[16 * 132];
    __shared__ float Bs[16 * 132];

    const int tid = threadIdx.x;
    const int m0 = blockIdx.y * 128;
    const int n0 = blockIdx.x * 128;
    const int lr = tid >> 2;      // 0..63
    const int lc = tid & 3;       // float4 column in k
    const int tx = tid & 15;
    const int ty = tid >> 4;

    const float* Ap = A + (size_t)(m0 + lr) * KDIM + lc * 4;
    const float* Bp = B + (size_t)(n0 + lr) * KDIM + lc * 4;

    float2 c2[8][4];
#pragma unroll
    for (int i = 0; i < 8; i++)
#pragma unroll
        for (int j = 0; j < 4; j++) c2[i][j] = make_float2(0.f, 0.f);

    float4 pa0 = *(const float4*)(Ap);
    float4 pa1 = *(const float4*)(Ap + (size_t)64 * KDIM);
    float4 pb0 = *(const float4*)(Bp);
    float4 pb1 = *(const float4*)(Bp + (size_t)64 * KDIM);

    const int KT = KDIM / 16;
    for (int kt = 0; kt < KT; kt++) {
        // stage current tile (transpose into [k][m]/[k][n])
        {
            const float* a0 = (const float*)&pa0;
            const float* a1 = (const float*)&pa1;
            const float* b0 = (const float*)&pb0;
            const float* b1 = (const float*)&pb1;
#pragma unroll
            for (int j = 0; j < 4; j++) {
                As[(lc * 4 + j) * 132 + lr]      = a0[j];
                As[(lc * 4 + j) * 132 + lr + 64] = a1[j];
                Bs[(lc * 4 + j) * 132 + lr]      = b0[j];
                Bs[(lc * 4 + j) * 132 + lr + 64] = b1[j];
            }
        }
        __syncthreads();
        if (kt + 1 < KT) {          // prefetch next tile into registers
            Ap += 16; Bp += 16;
            pa0 = *(const float4*)(Ap);
            pa1 = *(const float4*)(Ap + (size_t)64 * KDIM);
            pb0 = *(const float4*)(Bp);
            pb1 = *(const float4*)(Bp + (size_t)64 * KDIM);
        }
#pragma unroll
        for (int k = 0; k < 16; k++) {
            // 4+4 split fragments: rows {ty*4..+3, 64+ty*4..+3}, cols likewise
            float4 a0 = *(const float4*)&As[k * 132 + ty * 4];
            float4 a1 = *(const float4*)&As[k * 132 + 64 + ty * 4];
            float4 b0 = *(const float4*)&Bs[k * 132 + tx * 4];
            float4 b1 = *(const float4*)&Bs[k * 132 + 64 + tx * 4];
            float av[8] = {a0.x, a0.y, a0.z, a0.w, a1.x, a1.y, a1.z, a1.w};
            float2 bv[4] = {{b0.x, b0.y}, {b0.z, b0.w}, {b1.x, b1.y}, {b1.z, b1.w}};
#pragma unroll
            for (int i = 0; i < 8; i++) {
                float2 ad = make_float2(av[i], av[i]);
#pragma unroll
                for (int j = 0; j < 4; j++) c2[i][j] = ffma2(ad, bv[j], c2[i][j]);
            }
        }
        __syncthreads();
    }

    // epilogue: + bias, store. col(j): j<2 -> tx*4+2j ; j>=2 -> 64+tx*4+2(j-2)
    int ncol[4];
    float2 bb[4];
#pragma unroll
    for (int j = 0; j < 4; j++) {
        ncol[j] = n0 + ((j < 2) ? (tx * 4 + 2 * j) : (64 + tx * 4 + 2 * (j - 2)));
        bb[j] = make_float2(bias[ncol[j]], bias[ncol[j] + 1]);
    }

#pragma unroll
    for (int i = 0; i < 8; i++) {
        int r = m0 + ((i < 4) ? (ty * 4 + i) : (64 + ty * 4 + (i - 4)));
        size_t rbase;
        if (MODE == 0) {
            rbase = (size_t)r * GH;
        } else {
            int s = r >> 6, b = r & 63;                 // r = s*64+b
            rbase = ((size_t)(b * S_LEN + s)) * ODIM;
        }
#pragma unroll
        for (int j = 0; j < 4; j++) {
            float2 v = make_float2(c2[i][j].x + bb[j].x, c2[i][j].y + bb[j].y);
            *(float2*)&C[rbase + ncol[j]] = v;
        }
    }
}

// =============================================================================
// GRU scan: 4 groups x 32 CTAs. Group g owns batches [16g,16g+16); CTA slice
// owns 16 hidden units, weights REGISTER-resident for the whole scan.
// 256 threads = 16 k-interleave x 16 j. h in SMEM as [k][b16] stride-16
// (adjacent k rows hit disjoint bank halves -> conflict-free LDS.128).
// k ownership interleaved (k = kI + 16*m) so a warp's two half-warps read
// ADJACENT k rows. Exchange via g_hsT straight-copy + release/acquire barrier.
// =============================================================================
__global__ __launch_bounds__(256, 1)
void gru_scan(const float* __restrict__ w_hh, const float* __restrict__ b_hh)
{
    extern __shared__ float sm[];
    float* sh_h = sm;                       // 512*16 floats: h[k][b16]
    float* sred = sm + 512 * 16;            // 256*49 floats (partials)

    const int tid   = threadIdx.x;
    const int grp   = blockIdx.x >> 5;
    const int slice = blockIdx.x & 31;
    const int j0    = slice * 16;
    const int b0    = grp * 16;
    const int kI    = tid >> 4;             // k interleave offset 0..15
    const int jI    = tid & 15;             // hidden unit within slice

    // ---- register-resident weight slice: w[g][m] for k = kI + 16*m ---------
    float w[3][32];
#pragma unroll
    for (int g = 0; g < 3; g++) {
        const float* p = w_hh + (size_t)(g * HID + j0 + jI) * HID + kI;
#pragma unroll
        for (int m = 0; m < 32; m++) w[g][m] = p[16 * m];
    }

    // gate/reduce-stage identity: thread -> (hidden jj, batch bb)
    const int jj = tid >> 4;
    const int bb = tid & 15;
    const float bh_r = b_hh[j0 + jj];
    const float bh_z = b_hh[HID + j0 + jj];
    const float bh_n = b_hh[2 * HID + j0 + jj];

    // h0 = 0
    for (int i = tid; i < 512 * 16; i += 256) sh_h[i] = 0.f;
    __syncthreads();

    for (int s = 0; s < S_LEN; s++) {
        // prefetch gi for the gate stage (independent of this step's dots)
        const float* gip = g_gi + ((size_t)((b0 + bb) * S_LEN + s)) * GH + j0 + jj;
        float gir = gip[0], giz = gip[HID], gin = gip[2 * HID];

        // ---- partial dots over this thread's 32 interleaved k --------------
        float2 acc[8][3];
#pragma unroll
        for (int p = 0; p < 8; p++)
#pragma unroll
            for (int g = 0; g < 3; g++) acc[p][g] = make_float2(0.f, 0.f);

#pragma unroll
        for (int m = 0; m < 32; m++) {
            const float* hr = sh_h + (kI + 16 * m) * 16;
            float2 wr = make_float2(w[0][m], w[0][m]);
            float2 wz = make_float2(w[1][m], w[1][m]);
            float2 wn = make_float2(w[2][m], w[2][m]);
#pragma unroll
            for (int q = 0; q < 4; q++) {
                float4 h4 = *(const float4*)(hr + 4 * q);
                float2 h01 = make_float2(h4.x, h4.y);
                float2 h23 = make_float2(h4.z, h4.w);
                acc[2 * q][0]     = ffma2(h01, wr, acc[2 * q][0]);
                acc[2 * q][1]     = ffma2(h01, wz, acc[2 * q][1]);
                acc[2 * q][2]     = ffma2(h01, wn, acc[2 * q][2]);
                acc[2 * q + 1][0] = ffma2(h23, wr, acc[2 * q + 1][0]);
                acc[2 * q + 1][1] = ffma2(h23, wz, acc[2 * q + 1][1]);
                acc[2 * q + 1][2] = ffma2(h23, wn, acc[2 * q + 1][2]);
            }
        }

        // ---- dump partials: red[tid*49 + 3*b + g] (49 odd -> conflict-free)
        {
            float* rp = sred + tid * 49;
#pragma unroll
            for (int p = 0; p < 8; p++)
#pragma unroll
                for (int g = 0; g < 3; g++) {
                    rp[6 * p + g]     = acc[p][g].x;   // batch 2p
                    rp[6 * p + 3 + g] = acc[p][g].y;   // batch 2p+1
                }
        }
        __syncthreads();

        // ---- fused reduce(16 k-chunks) + gates + state update --------------
        float ghr = bh_r, ghz = bh_z, ghn = bh_n;
#pragma unroll
        for (int kc = 0; kc < 16; kc++) {
            const float* rp = sred + (kc * 16 + jj) * 49 + 3 * bb;
            ghr += rp[0]; ghz += rp[1]; ghn += rp[2];
        }
        float r = 1.f / (1.f + __expf(-(gir + ghr)));
        float z = 1.f / (1.f + __expf(-(giz + ghz)));
        float n = tanhf(gin + r * ghn);
        float hp = sh_h[(j0 + jj) * 16 + bb];
        float hn = (1.f - z) * n + z * hp;

        // exchange layout write (read by peers next step)
        g_hsT[(((size_t)s * 4 + grp) * HID + j0 + jj) * 16 + bb] = hn;
        __syncthreads();

        // ---- group barrier: release-arrive, then (overlap) GEMM2 store -----
        unsigned* ctr = &g_bar[grp * S_LEN + s];
        if (tid == 0)
            asm volatile("red.release.gpu.global.add.u32 [%0], 1;" :: "l"(ctr) : "memory");

        // GEMM2 layout write (only needed after kernel end; overlaps barrier)
        g_hs[((size_t)s * BATCH + b0 + bb) * HID + j0 + jj] = hn;

        if (tid == 0) {
            unsigned v;
            do {
                asm volatile("ld.acquire.gpu.global.u32 %0, [%1];"
                             : "=r"(v) : "l"(ctr) : "memory");
            } while (v < 32u);
        }
        __syncthreads();

        // ---- reload full h for next step (straight float4 copy) ------------
        if (s + 1 < S_LEN) {
            const float4* src = (const float4*)(g_hsT + ((size_t)s * 4 + grp) * HID * 16);
            float4* dst = (float4*)sh_h;
#pragma unroll
            for (int i = 0; i < 8; i++) dst[tid + 256 * i] = src[tid + 256 * i];
            __syncthreads();
        }
    }
}

// =============================================================================
extern "C" void kernel_launch(void* const* d_in, const int* in_sizes, int n_in,
                              void* d_out, int out_size)
{
    (void)in_sizes; (void)n_in; (void)out_size;
    const float* x     = (const float*)d_in[0];   // [64,512,256]
    const float* w_ih  = (const float*)d_in[1];   // [1536,256]
    const float* w_hh  = (const float*)d_in[2];   // [1536,512]
    const float* b_ih  = (const float*)d_in[3];   // [1536]
    const float* b_hh  = (const float*)d_in[4];   // [1536]
    const float* w_out = (const float*)d_in[5];   // [512,512]
    const float* b_out = (const float*)d_in[6];   // [512]
    float* out = (float*)d_out;                   // [64,512,256,2]

    void *p_gi = nullptr, *p_hs = nullptr, *p_bar = nullptr;
    cudaGetSymbolAddress(&p_gi, g_gi);
    cudaGetSymbolAddress(&p_hs, g_hs);
    cudaGetSymbolAddress(&p_bar, g_bar);

    // reset barrier counters (captured into the graph, runs every replay)
    cudaMemsetAsync(p_bar, 0, sizeof(unsigned) * 4 * S_LEN);

    const int scan_smem = (512 * 16 + 256 * 49) * 4;   // 82944 B
    cudaFuncSetAttribute(gru_scan, cudaFuncAttributeMaxDynamicSharedMemorySize, scan_smem);

    // Phase 1: gi = x @ w_ih^T + b_ih   (M=32768, N=1536, K=256)
    gemm_tn<IDIM, 0><<<dim3(GH / 128, (BATCH * S_LEN) / 128), 256>>>(
        x, w_ih, b_ih, (float*)p_gi);

    // Phase 2: 512-step GRU scan (persistent, 128 CTAs, group barriers)
    gru_scan<<<128, 256, scan_smem>>>(w_hh, b_hh);

    // Phase 3: out = hs @ w_out^T + b_out   (M=32768, N=512, K=512)
    gemm_tn<HID, 1><<<dim3(ODIM / 128, (BATCH * S_LEN) / 128), 256>>>(
        (const float*)p_hs, w_out, b_out, out);
}